// round 6
// baseline (speedup 1.0000x reference)
#include <cuda_runtime.h>
#include <cstdint>

// FPS: B=8, N=65536, select 1024. One 8-CTA cluster per batch (16 probed).
// st.async+mbarrier exchange carries winner coords (no pivot L2 fetch);
// main loop tracks max only; index recovered divergently, redux kept converged.

#define FPS_B  8
#define FPS_N  65536
#define FPS_NP 1024
#define FPS_T  1024
#define NW     (FPS_T / 32)
#define SLOT_B 48           // bytes per exchange slot (key @+0, xy @+16, z @+24)

__device__ __forceinline__ uint64_t pack2(float a, float b) {
    uint64_t r; asm("mov.b64 %0, {%1, %2};" : "=l"(r) : "f"(a), "f"(b)); return r;
}
__device__ __forceinline__ void unpack2(uint64_t v, float& a, float& b) {
    asm("mov.b64 {%0, %1}, %2;" : "=f"(a), "=f"(b) : "l"(v));
}
__device__ __forceinline__ uint64_t add2(uint64_t a, uint64_t b) {
    uint64_t r; asm("add.rn.f32x2 %0, %1, %2;" : "=l"(r) : "l"(a), "l"(b)); return r;
}
__device__ __forceinline__ uint64_t mul2(uint64_t a, uint64_t b) {
    uint64_t r; asm("mul.rn.f32x2 %0, %1, %2;" : "=l"(r) : "l"(a), "l"(b)); return r;
}
__device__ __forceinline__ uint32_t ctarank() {
    uint32_t r; asm("mov.u32 %0, %%cluster_ctarank;" : "=r"(r)); return r;
}
__device__ __forceinline__ uint32_t smem_u32(const void* p) {
    uint32_t a;
    asm("{ .reg .u64 t; cvta.to.shared.u64 t, %1; cvt.u32.u64 %0, t; }" : "=r"(a) : "l"(p));
    return a;
}
__device__ __forceinline__ uint32_t redux_max_u32(uint32_t v) {
    uint32_t r; asm("redux.sync.max.u32 %0, %1, 0xFFFFFFFF;" : "=r"(r) : "r"(v)); return r;
}
__device__ __forceinline__ uint32_t redux_min_u32(uint32_t v) {
    uint32_t r; asm("redux.sync.min.u32 %0, %1, 0xFFFFFFFF;" : "=r"(r) : "r"(v)); return r;
}
__device__ __forceinline__ void mbar_init(uint32_t mbar, uint32_t cnt) {
    asm volatile("mbarrier.init.shared.b64 [%0], %1;" :: "r"(mbar), "r"(cnt) : "memory");
}
__device__ __forceinline__ void mbar_expect_tx(uint32_t mbar, uint32_t bytes) {
    asm volatile("mbarrier.arrive.expect_tx.shared.b64 _, [%0], %1;"
                 :: "r"(mbar), "r"(bytes) : "memory");
}
__device__ __forceinline__ void mbar_wait(uint32_t mbar, uint32_t parity) {
    asm volatile(
        "{\n\t"
        ".reg .pred P;\n\t"
        "WL_%=:\n\t"
        "mbarrier.try_wait.parity.acquire.cluster.shared::cta.b64 P, [%0], %1, 0x989680;\n\t"
        "@P bra.uni WD_%=;\n\t"
        "bra.uni WL_%=;\n\t"
        "WD_%=:\n\t"
        "}"
        :: "r"(mbar), "r"(parity) : "memory");
}
__device__ __forceinline__ uint32_t mapa32(uint32_t laddr, uint32_t rank) {
    uint32_t r;
    asm("mapa.shared::cluster.u32 %0, %1, %2;" : "=r"(r) : "r"(laddr), "r"(rank));
    return r;
}
__device__ __forceinline__ void st_async_u64(uint32_t raddr, uint64_t v, uint32_t rmbar) {
    asm volatile("st.async.shared::cluster.mbarrier::complete_tx::bytes.b64 [%0], %1, [%2];"
                 :: "r"(raddr), "l"(v), "r"(rmbar) : "memory");
}
__device__ __forceinline__ uint64_t lds_u64(uint32_t addr) {
    uint64_t v; asm volatile("ld.shared.u64 %0, [%1];" : "=l"(v) : "r"(addr)); return v;
}
__device__ __forceinline__ void lds_v2_u64(uint32_t addr, uint64_t& a, uint64_t& b) {
    asm volatile("ld.shared.v2.u64 {%0, %1}, [%2];" : "=l"(a), "=l"(b) : "r"(addr));
}

template<int CL>
__global__ void __launch_bounds__(FPS_T, 1)
fps_kernel(const float* __restrict__ pts, float* __restrict__ out) {
    constexpr int PT    = FPS_N / (CL * FPS_T);
    constexpr int NF4   = PT / 4;
    constexpr int NPAIR = PT / 2;
    constexpr uint32_t XBYTES = 24u * CL;          // 3x u64 per peer

    const int b      = blockIdx.x / CL;
    const uint32_t k = ctarank();
    const int tid    = threadIdx.x;
    const int lane   = tid & 31;
    const int wid    = tid >> 5;

    const float* __restrict__ xb = pts + (size_t)b * 3 * FPS_N;
    const float4* __restrict__ x4 = (const float4*)(xb);
    const float4* __restrict__ y4 = (const float4*)(xb + FPS_N);
    const float4* __restrict__ z4 = (const float4*)(xb + 2 * FPS_N);

    uint64_t xp[NPAIR], yp[NPAIR], zp[NPAIR];
    float dist[PT];
    int pbase[NF4];

#pragma unroll
    for (int j = 0; j < NF4; j++) {
        int f = (int)k * (FPS_N / 4 / CL) + tid + FPS_T * j;
        pbase[j] = 4 * f;
        float4 vx = x4[f], vy = y4[f], vz = z4[f];
        xp[2*j+0] = pack2(vx.x, vx.y);  xp[2*j+1] = pack2(vx.z, vx.w);
        yp[2*j+0] = pack2(vy.x, vy.y);  yp[2*j+1] = pack2(vy.z, vy.w);
        zp[2*j+0] = pack2(vz.x, vz.y);  zp[2*j+1] = pack2(vz.z, vz.w);
    }
#pragma unroll
    for (int p = 0; p < PT; p++) dist[p] = 1e10f;

    __shared__ uint64_t s_wkey[NW];                     // (d<<32)|~i per warp
    __shared__ uint64_t s_wxy[NW];
    __shared__ uint64_t s_wz[NW];
    __shared__ alignas(16) unsigned char s_slot[2][CL * SLOT_B];
    __shared__ alignas(8)  uint64_t s_mbar[2];
    __shared__ uint32_t s_hist[FPS_NP];

    const uint32_t mb0 = smem_u32(&s_mbar[0]);
    const uint32_t mb1 = smem_u32(&s_mbar[1]);
    const uint32_t pair0 = smem_u32(&s_slot[0][0]);
    const uint32_t pair1 = smem_u32(&s_slot[1][0]);

    uint32_t r_slot0 = 0, r_slot1 = 0, r_mb0 = 0, r_mb1 = 0;
    if (wid == 0 && lane < CL) {
        r_slot0 = mapa32(pair0 + SLOT_B * k, (uint32_t)lane);
        r_slot1 = mapa32(pair1 + SLOT_B * k, (uint32_t)lane);
        r_mb0   = mapa32(mb0, (uint32_t)lane);
        r_mb1   = mapa32(mb1, (uint32_t)lane);
    }

    if (tid == 0) {
        mbar_init(mb0, 1);
        mbar_init(mb1, 1);
        mbar_expect_tx(mb0, XBYTES);
        mbar_expect_tx(mb1, XBYTES);
        s_hist[0] = 0;
    }
    __syncthreads();
    asm volatile("barrier.cluster.arrive.aligned;" ::: "memory");
    asm volatile("barrier.cluster.wait.aligned;"   ::: "memory");

    float px = __ldg(&xb[0]);
    float py = __ldg(&xb[FPS_N]);
    float pz = __ldg(&xb[2 * FPS_N]);

    for (int it = 1; it < FPS_NP; it++) {
        const int u        = it - 1;
        const int buf      = u & 1;
        const uint32_t par = (u >> 1) & 1;
        const uint32_t mb     = buf ? mb1 : mb0;
        const uint32_t pbuf   = buf ? pair1 : pair0;
        const uint32_t r_slot = buf ? r_slot1 : r_slot0;
        const uint32_t r_mb   = buf ? r_mb1 : r_mb0;

        uint64_t npx = pack2(-px, -px);
        uint64_t npy = pack2(-py, -py);
        uint64_t npz = pack2(-pz, -pz);

        // main path: dist update + running max only (no index tracking)
        float bma = -1.0f, bmb = -1.0f;
#pragma unroll
        for (int q = 0; q < NPAIR; q++) {
            uint64_t dx = add2(xp[q], npx);        // add(x,-p) bitwise == sub(x,p)
            uint64_t dy = add2(yp[q], npy);
            uint64_t dz = add2(zp[q], npz);
            // XLA order: (dx^2 + dy^2) + dz^2, separate .rn rounding
            uint64_t s = add2(add2(mul2(dx, dx), mul2(dy, dy)), mul2(dz, dz));
            float d0, d1; unpack2(s, d0, d1);
            const int p = 2 * q;
            float n0 = fminf(dist[p],     d0);  dist[p]     = n0;  bma = fmaxf(bma, n0);
            float n1 = fminf(dist[p + 1], d1);  dist[p + 1] = n1;  bmb = fmaxf(bmb, n1);
        }
        const float bestd = fmaxf(bma, bmb);

        // warp argmax (dists >= 0: u32 order == float order)
        uint32_t db   = __float_as_uint(bestd);
        uint32_t wmax = redux_max_u32(db);

        // divergent recovery scan (no sync inside); redux stays converged below
        uint32_t cand = 0xFFFFFFFFu;
        uint64_t cxy = 0, czz = 0;
        if (db == wmax) {
            int fidx = -1; float fx = 0.f, fy = 0.f, fz = 0.f;
#pragma unroll
            for (int q = NPAIR - 1; q >= 0; q--) {
#pragma unroll
                for (int e = 1; e >= 0; e--) {
                    const int p = 2 * q + e;
                    if (__float_as_uint(dist[p]) == wmax) {
                        fidx = pbase[q >> 1] + 2 * (q & 1) + e;
                        float a0, a1;
                        unpack2(xp[q], a0, a1); fx = e ? a1 : a0;
                        unpack2(yp[q], a0, a1); fy = e ? a1 : a0;
                        unpack2(zp[q], a0, a1); fz = e ? a1 : a0;
                    }
                }
            }
            cand = (uint32_t)fidx;
            cxy  = pack2(fx, fy);
            czz  = pack2(fz, 0.f);
        }
        uint32_t wmin = redux_min_u32(cand);        // CONVERGED: all 32 lanes
        if (cand == wmin) {                         // unique lane (indices disjoint)
            s_wkey[wid] = ((uint64_t)wmax << 32) | (uint64_t)(~wmin);
            s_wxy[wid]  = cxy;
            s_wz[wid]   = czz;
        }

        if (wid == 0) {
            asm volatile("bar.sync 1, %0;" :: "r"(FPS_T) : "memory");
            uint64_t wkey = s_wkey[lane];           // NW == 32
            uint32_t d  = (uint32_t)(wkey >> 32);
            uint32_t ni = (uint32_t)wkey;
            uint32_t m   = redux_max_u32(d);
            uint32_t nim = redux_max_u32((d == m) ? ni : 0u);     // max ~i == min i
            uint32_t ws  = redux_max_u32((d == m && ni == nim) ? (uint32_t)lane : 0u);
            uint64_t xy = s_wxy[ws];
            uint64_t zz = s_wz[ws];
            if (lane < CL) {
                uint64_t key = ((uint64_t)m << 32) | (uint64_t)nim;
                st_async_u64(r_slot,      key, r_mb);
                st_async_u64(r_slot + 16, xy,  r_mb);
                st_async_u64(r_slot + 24, zz,  r_mb);
            }
        } else {
            asm volatile("bar.arrive 1, %0;" :: "r"(FPS_T) : "memory");
        }

        mbar_wait(mb, par);

        // per-warp reduce of CL exchanged candidates (all redux converged)
        uint32_t d = 0, ni = 0;
        if (lane < CL) {
            uint64_t kk = lds_u64(pbuf + SLOT_B * (uint32_t)lane);
            d  = (uint32_t)(kk >> 32);
            ni = (uint32_t)kk;
        }
        uint32_t dm  = redux_max_u32(d);
        uint32_t nim = redux_max_u32((lane < CL && d == dm) ? ni : 0u);
        uint32_t rs  = redux_max_u32((lane < CL && d == dm && ni == nim) ? (uint32_t)lane : 0u);
        const int widx = (int)(~nim);

        uint64_t wxy, wzz;
        lds_v2_u64(pbuf + SLOT_B * rs + 16, wxy, wzz);
        float zpad;
        unpack2(wxy, px, py);
        unpack2(wzz, pz, zpad);

        if (tid == 0) {
            s_hist[it] = (uint32_t)widx;
            mbar_expect_tx(mb, XBYTES);             // next phase of this buffer
        }
    }

    // final gather: rank-0 CTA writes (3, 1024) for its batch
    __syncthreads();
    if (k == 0) {
        for (int i = tid; i < 3 * FPS_NP; i += FPS_T) {
            int ip = i & (FPS_NP - 1);
            int c  = i >> 10;
            uint32_t idx = s_hist[ip];
            out[((size_t)b * 3 + c) * FPS_NP + ip] = xb[(size_t)c * FPS_N + idx];
        }
    }
}

extern "C" void kernel_launch(void* const* d_in, const int* in_sizes, int n_in,
                              void* d_out, int out_size) {
    const float* pts = (const float*)d_in[0];
    float* out = (float*)d_out;

    cudaLaunchConfig_t cfg = {};
    cfg.blockDim = dim3(FPS_T, 1, 1);
    cfg.stream = 0;
    cudaLaunchAttribute at[1];
    at[0].id = cudaLaunchAttributeClusterDimension;
    cfg.attrs = at;
    cfg.numAttrs = 1;

    bool ok16 = false;
    if (cudaFuncSetAttribute(fps_kernel<16>,
                             cudaFuncAttributeNonPortableClusterSizeAllowed, 1) == cudaSuccess) {
        cfg.gridDim = dim3(FPS_B * 16, 1, 1);
        at[0].val.clusterDim = {16, 1, 1};
        int nc = 0;
        if (cudaOccupancyMaxActiveClusters(&nc, fps_kernel<16>, &cfg) == cudaSuccess &&
            nc >= FPS_B)
            ok16 = true;
    }
    (void)cudaGetLastError();

    if (ok16) {
        cfg.gridDim = dim3(FPS_B * 16, 1, 1);
        at[0].val.clusterDim = {16, 1, 1};
        cudaLaunchKernelEx(&cfg, fps_kernel<16>, pts, out);
    } else {
        cfg.gridDim = dim3(FPS_B * 8, 1, 1);
        at[0].val.clusterDim = {8, 1, 1};
        cudaLaunchKernelEx(&cfg, fps_kernel<8>, pts, out);
    }
}

// round 7
// speedup vs baseline: 1.0330x; 1.0330x over previous
#include <cuda_runtime.h>
#include <cstdint>

// FPS: B=8, N=65536, select 1024. One cluster per batch (16 probed, 8 fallback).
// Round-4 hot loop (SEL-chain argmax). Winner-lane coord prefetch overlapped
// with the reduce via a second bar; coords ride the st.async exchange message.

#define FPS_B  8
#define FPS_N  65536
#define FPS_NP 1024
#define FPS_T  1024
#define NW     (FPS_T / 32)
#define SLOT_B 48           // key @+0, xy @+16, z @+24 (conflict-free stride)

__device__ __forceinline__ uint64_t pack2(float a, float b) {
    uint64_t r; asm("mov.b64 %0, {%1, %2};" : "=l"(r) : "f"(a), "f"(b)); return r;
}
__device__ __forceinline__ void unpack2(uint64_t v, float& a, float& b) {
    asm("mov.b64 {%0, %1}, %2;" : "=f"(a), "=f"(b) : "l"(v));
}
__device__ __forceinline__ uint64_t add2(uint64_t a, uint64_t b) {
    uint64_t r; asm("add.rn.f32x2 %0, %1, %2;" : "=l"(r) : "l"(a), "l"(b)); return r;
}
__device__ __forceinline__ uint64_t mul2(uint64_t a, uint64_t b) {
    uint64_t r; asm("mul.rn.f32x2 %0, %1, %2;" : "=l"(r) : "l"(a), "l"(b)); return r;
}
__device__ __forceinline__ uint32_t ctarank() {
    uint32_t r; asm("mov.u32 %0, %%cluster_ctarank;" : "=r"(r)); return r;
}
__device__ __forceinline__ uint32_t smem_u32(const void* p) {
    uint32_t a;
    asm("{ .reg .u64 t; cvta.to.shared.u64 t, %1; cvt.u32.u64 %0, t; }" : "=r"(a) : "l"(p));
    return a;
}
__device__ __forceinline__ uint32_t redux_max_u32(uint32_t v) {
    uint32_t r; asm("redux.sync.max.u32 %0, %1, 0xFFFFFFFF;" : "=r"(r) : "r"(v)); return r;
}
__device__ __forceinline__ uint32_t redux_min_u32(uint32_t v) {
    uint32_t r; asm("redux.sync.min.u32 %0, %1, 0xFFFFFFFF;" : "=r"(r) : "r"(v)); return r;
}
__device__ __forceinline__ void mbar_init(uint32_t mbar, uint32_t cnt) {
    asm volatile("mbarrier.init.shared.b64 [%0], %1;" :: "r"(mbar), "r"(cnt) : "memory");
}
__device__ __forceinline__ void mbar_expect_tx(uint32_t mbar, uint32_t bytes) {
    asm volatile("mbarrier.arrive.expect_tx.shared.b64 _, [%0], %1;"
                 :: "r"(mbar), "r"(bytes) : "memory");
}
__device__ __forceinline__ void mbar_wait(uint32_t mbar, uint32_t parity) {
    asm volatile(
        "{\n\t"
        ".reg .pred P;\n\t"
        "WL_%=:\n\t"
        "mbarrier.try_wait.parity.acquire.cluster.shared::cta.b64 P, [%0], %1, 0x989680;\n\t"
        "@P bra.uni WD_%=;\n\t"
        "bra.uni WL_%=;\n\t"
        "WD_%=:\n\t"
        "}"
        :: "r"(mbar), "r"(parity) : "memory");
}
__device__ __forceinline__ uint32_t mapa32(uint32_t laddr, uint32_t rank) {
    uint32_t r;
    asm("mapa.shared::cluster.u32 %0, %1, %2;" : "=r"(r) : "r"(laddr), "r"(rank));
    return r;
}
__device__ __forceinline__ void st_async_u64(uint32_t raddr, uint64_t v, uint32_t rmbar) {
    asm volatile("st.async.shared::cluster.mbarrier::complete_tx::bytes.b64 [%0], %1, [%2];"
                 :: "r"(raddr), "l"(v), "r"(rmbar) : "memory");
}
__device__ __forceinline__ uint64_t lds_u64(uint32_t addr) {
    uint64_t v; asm volatile("ld.shared.u64 %0, [%1];" : "=l"(v) : "r"(addr)); return v;
}
__device__ __forceinline__ void lds_v2_u64(uint32_t addr, uint64_t& a, uint64_t& b) {
    asm volatile("ld.shared.v2.u64 {%0, %1}, [%2];" : "=l"(a), "=l"(b) : "r"(addr));
}

template<int CL>
__global__ void __launch_bounds__(FPS_T, 1)
fps_kernel(const float* __restrict__ pts, float* __restrict__ out) {
    constexpr int PT    = FPS_N / (CL * FPS_T);
    constexpr int NF4   = PT / 4;
    constexpr int NPAIR = PT / 2;
    constexpr uint32_t XBYTES = 24u * CL;          // 3x u64 per peer

    const int b      = blockIdx.x / CL;
    const uint32_t k = ctarank();
    const int tid    = threadIdx.x;
    const int lane   = tid & 31;
    const int wid    = tid >> 5;

    const float* __restrict__ xb = pts + (size_t)b * 3 * FPS_N;
    const float4* __restrict__ x4 = (const float4*)(xb);
    const float4* __restrict__ y4 = (const float4*)(xb + FPS_N);
    const float4* __restrict__ z4 = (const float4*)(xb + 2 * FPS_N);

    uint64_t xp[NPAIR], yp[NPAIR], zp[NPAIR];
    float dist[PT];
    int pbase[NF4];

#pragma unroll
    for (int j = 0; j < NF4; j++) {
        int f = (int)k * (FPS_N / 4 / CL) + tid + FPS_T * j;
        pbase[j] = 4 * f;
        float4 vx = x4[f], vy = y4[f], vz = z4[f];
        xp[2*j+0] = pack2(vx.x, vx.y);  xp[2*j+1] = pack2(vx.z, vx.w);
        yp[2*j+0] = pack2(vy.x, vy.y);  yp[2*j+1] = pack2(vy.z, vy.w);
        zp[2*j+0] = pack2(vz.x, vz.y);  zp[2*j+1] = pack2(vz.z, vz.w);
    }
#pragma unroll
    for (int p = 0; p < PT; p++) dist[p] = 1e10f;

    __shared__ uint64_t s_wkey[NW];                       // (d<<32)|~i per warp
    __shared__ alignas(16) uint64_t s_wc[NW][2];          // winner coords {xy, z}
    __shared__ alignas(16) unsigned char s_slot[2][CL * SLOT_B];
    __shared__ alignas(8)  uint64_t s_mbar[2];
    __shared__ uint32_t s_hist[FPS_NP];

    const uint32_t mb0 = smem_u32(&s_mbar[0]);
    const uint32_t mb1 = smem_u32(&s_mbar[1]);
    const uint32_t pair0 = smem_u32(&s_slot[0][0]);
    const uint32_t pair1 = smem_u32(&s_slot[1][0]);

    uint32_t r_slot0 = 0, r_slot1 = 0, r_mb0 = 0, r_mb1 = 0;
    if (wid == 0 && lane < CL) {
        r_slot0 = mapa32(pair0 + SLOT_B * k, (uint32_t)lane);
        r_slot1 = mapa32(pair1 + SLOT_B * k, (uint32_t)lane);
        r_mb0   = mapa32(mb0, (uint32_t)lane);
        r_mb1   = mapa32(mb1, (uint32_t)lane);
    }

    if (tid == 0) {
        mbar_init(mb0, 1);
        mbar_init(mb1, 1);
        mbar_expect_tx(mb0, XBYTES);
        mbar_expect_tx(mb1, XBYTES);
        s_hist[0] = 0;
    }
    __syncthreads();
    asm volatile("barrier.cluster.arrive.aligned;" ::: "memory");
    asm volatile("barrier.cluster.wait.aligned;"   ::: "memory");

    float px = __ldg(&xb[0]);
    float py = __ldg(&xb[FPS_N]);
    float pz = __ldg(&xb[2 * FPS_N]);

    for (int it = 1; it < FPS_NP; it++) {
        const int u        = it - 1;
        const int buf      = u & 1;
        const uint32_t par = (u >> 1) & 1;
        const uint32_t mb     = buf ? mb1 : mb0;
        const uint32_t pbuf   = buf ? pair1 : pair0;
        const uint32_t r_slot = buf ? r_slot1 : r_slot0;
        const uint32_t r_mb   = buf ? r_mb1 : r_mb0;

        uint64_t npx = pack2(-px, -px);
        uint64_t npy = pack2(-py, -py);
        uint64_t npz = pack2(-pz, -pz);

        // round-4 hot loop: SEL-chain index tracking (no recovery scan)
        float bestd  = -1.0f;
        int   bestid = 0;
#pragma unroll
        for (int q = 0; q < NPAIR; q++) {
            uint64_t dx = add2(xp[q], npx);        // add(x,-p) bitwise == sub(x,p)
            uint64_t dy = add2(yp[q], npy);
            uint64_t dz = add2(zp[q], npz);
            // XLA order: (dx^2 + dy^2) + dz^2, separate .rn rounding
            uint64_t s = add2(add2(mul2(dx, dx), mul2(dy, dy)), mul2(dz, dz));
            float d0, d1; unpack2(s, d0, d1);
            const int p   = 2 * q;
            const int idx = pbase[q >> 1] + 2 * (q & 1);
            float n0 = fminf(dist[p], d0);     dist[p]     = n0;
            if (n0 > bestd) { bestd = n0; bestid = idx; }      // strict >: first idx wins
            float n1 = fminf(dist[p + 1], d1); dist[p + 1] = n1;
            if (n1 > bestd) { bestd = n1; bestid = idx + 1; }
        }

        // warp argmax (dists >= 0: u32 order == float order); first-index tie-break
        uint32_t db   = __float_as_uint(bestd);
        uint32_t wmax = redux_max_u32(db);
        uint32_t cand = (db == wmax) ? (uint32_t)bestid : 0xFFFFFFFFu;
        uint32_t wmin = redux_min_u32(cand);
        const bool win = (db == wmax) && ((uint32_t)bestid == wmin);  // unique lane

        float cx = 0.f, cy = 0.f, cz = 0.f;
        if (win) {
            s_wkey[wid] = ((uint64_t)wmax << 32) | (uint64_t)(~wmin);
            // prefetch candidate coords: overlaps bar1 + warp0 reduce
            cx = __ldcg(&xb[wmin]);
            cy = __ldcg(&xb[FPS_N + wmin]);
            cz = __ldcg(&xb[2 * FPS_N + wmin]);
        }

        if (wid == 0) {
            asm volatile("bar.sync 1, %0;" :: "r"(FPS_T) : "memory");
            uint64_t wkey = s_wkey[lane];          // NW == 32
            uint32_t d  = (uint32_t)(wkey >> 32);
            uint32_t ni = (uint32_t)wkey;
            uint32_t m   = redux_max_u32(d);
            uint32_t nim = redux_max_u32((d == m) ? ni : 0u);    // max ~i == min i
            uint32_t ws  = redux_max_u32((d == m && ni == nim) ? (uint32_t)lane : 0u);
            if (win) {                             // warp0's own winner (if any)
                ulonglong2 cc; cc.x = pack2(cx, cy); cc.y = pack2(cz, 0.f);
                *(ulonglong2*)&s_wc[wid][0] = cc;
            }
            asm volatile("bar.sync 2, %0;" :: "r"(FPS_T) : "memory");
            uint64_t xy, zz;
            lds_v2_u64(smem_u32(&s_wc[ws][0]), xy, zz);
            if (lane < CL) {
                uint64_t key = ((uint64_t)m << 32) | (uint64_t)nim;
                st_async_u64(r_slot,      key, r_mb);
                st_async_u64(r_slot + 16, xy,  r_mb);
                st_async_u64(r_slot + 24, zz,  r_mb);
            }
        } else {
            asm volatile("bar.arrive 1, %0;" :: "r"(FPS_T) : "memory");
            if (win) {                             // STS waits on the LDGs
                ulonglong2 cc; cc.x = pack2(cx, cy); cc.y = pack2(cz, 0.f);
                *(ulonglong2*)&s_wc[wid][0] = cc;
            }
            asm volatile("bar.arrive 2, %0;" :: "r"(FPS_T) : "memory");
        }

        mbar_wait(mb, par);

        // per-warp reduce of CL exchanged candidates (all redux converged)
        uint32_t d = 0, ni = 0;
        if (lane < CL) {
            uint64_t kk = lds_u64(pbuf + SLOT_B * (uint32_t)lane);
            d  = (uint32_t)(kk >> 32);
            ni = (uint32_t)kk;
        }
        uint32_t dm  = redux_max_u32(d);
        uint32_t nim = redux_max_u32((lane < CL && d == dm) ? ni : 0u);
        uint32_t rs  = redux_max_u32((lane < CL && d == dm && ni == nim) ? (uint32_t)lane : 0u);
        const int widx = (int)(~nim);

        uint64_t wxy, wzz;
        lds_v2_u64(pbuf + SLOT_B * rs + 16, wxy, wzz);
        float zpad;
        unpack2(wxy, px, py);
        unpack2(wzz, pz, zpad);

        if (tid == 0) {
            s_hist[it] = (uint32_t)widx;
            mbar_expect_tx(mb, XBYTES);            // next phase of this buffer
        }
    }

    // final gather: rank-0 CTA writes (3, 1024) for its batch
    __syncthreads();
    if (k == 0) {
        for (int i = tid; i < 3 * FPS_NP; i += FPS_T) {
            int ip = i & (FPS_NP - 1);
            int c  = i >> 10;
            uint32_t idx = s_hist[ip];
            out[((size_t)b * 3 + c) * FPS_NP + ip] = xb[(size_t)c * FPS_N + idx];
        }
    }
}

extern "C" void kernel_launch(void* const* d_in, const int* in_sizes, int n_in,
                              void* d_out, int out_size) {
    const float* pts = (const float*)d_in[0];
    float* out = (float*)d_out;

    cudaLaunchConfig_t cfg = {};
    cfg.blockDim = dim3(FPS_T, 1, 1);
    cfg.stream = 0;
    cudaLaunchAttribute at[1];
    at[0].id = cudaLaunchAttributeClusterDimension;
    cfg.attrs = at;
    cfg.numAttrs = 1;

    // probe 16-CTA non-portable clusters (host-side, capture-safe)
    bool ok16 = false;
    if (cudaFuncSetAttribute(fps_kernel<16>,
                             cudaFuncAttributeNonPortableClusterSizeAllowed, 1) == cudaSuccess) {
        int maxcs = 0;
        cudaLaunchConfig_t pcfg = cfg;
        pcfg.gridDim = dim3(FPS_B * 16, 1, 1);
        if (cudaOccupancyMaxPotentialClusterSize(&maxcs, fps_kernel<16>, &pcfg) == cudaSuccess &&
            maxcs >= 16) {
            at[0].val.clusterDim = {16, 1, 1};
            pcfg.attrs = at; pcfg.numAttrs = 1;
            int nc = 0;
            if (cudaOccupancyMaxActiveClusters(&nc, fps_kernel<16>, &pcfg) == cudaSuccess &&
                nc >= FPS_B)
                ok16 = true;
        }
    }
    (void)cudaGetLastError();

    if (ok16) {
        cfg.gridDim = dim3(FPS_B * 16, 1, 1);
        at[0].val.clusterDim = {16, 1, 1};
        cudaLaunchKernelEx(&cfg, fps_kernel<16>, pts, out);
    } else {
        cfg.gridDim = dim3(FPS_B * 8, 1, 1);
        at[0].val.clusterDim = {8, 1, 1};
        cudaLaunchKernelEx(&cfg, fps_kernel<8>, pts, out);
    }
}